// round 8
// baseline (speedup 1.0000x reference)
#include <cuda_runtime.h>
#include <cuda_bf16.h>
#include <math.h>
#include <stdint.h>

// Problem constants
#define BB   2
#define NN   2048
#define CC   512
#define HEADS 8
#define DH   64
#define WIN  64
#define RR   8
#define MTOT (BB*NN)        // 4096
#define QKVC (3*CC)         // 1536
#define LORA_SC 0.25f

// Scratch (device globals)
__device__ float g_weff[QKVC*CC];   // effective W_qkv, TRANSPOSED [n][k], tf32-rounded
__device__ float g_wout[CC*CC];     // effective W_out, TRANSPOSED [n][k], tf32-rounded
__device__ float g_qkv[MTOT*QKVC];  // gemm1 output, tf32-rounded
__device__ float g_att[MTOT*CC];    // attention output, tf32-rounded

__device__ __forceinline__ uint32_t f2tf32(float f) {
    uint32_t r;
    asm volatile("cvt.rna.tf32.f32 %0, %1;" : "=r"(r) : "f"(f));
    return r;
}
__device__ __forceinline__ float rnd_tf32(float f) { return __uint_as_float(f2tf32(f)); }
__device__ __forceinline__ uint32_t u2tf32(uint32_t u) { return f2tf32(__uint_as_float(u)); }

__device__ __forceinline__ void cp16(uint32_t saddr, const void* gptr) {
    asm volatile("cp.async.ca.shared.global [%0], [%1], 16;\n" :: "r"(saddr), "l"(gptr));
}
#define CP_COMMIT asm volatile("cp.async.commit_group;\n" ::: "memory")
#define CP_WAIT(n) asm volatile("cp.async.wait_group %0;\n" :: "n"(n) : "memory")

#define MMA_TF32(acc, a0,a1,a2,a3, b0,b1)                                     \
    asm volatile(                                                              \
        "mma.sync.aligned.m16n8k8.row.col.f32.tf32.tf32.f32 "                  \
        "{%0,%1,%2,%3}, {%4,%5,%6,%7}, {%8,%9}, {%0,%1,%2,%3};\n"              \
        : "+f"(acc[0]), "+f"(acc[1]), "+f"(acc[2]), "+f"(acc[3])               \
        : "r"(a0), "r"(a1), "r"(a2), "r"(a3), "r"(b0), "r"(b1))

// ---------------------------------------------------------------------------
// Prep: fold LoRA into transposed tf32-rounded effective weights (weights only)
// ---------------------------------------------------------------------------
__global__ void prep_kernel(const float* __restrict__ Wq,
                            const float* __restrict__ Aq,
                            const float* __restrict__ Bq,
                            const float* __restrict__ Wo,
                            const float* __restrict__ Ao,
                            const float* __restrict__ Bo) {
    int idx = blockIdx.x * blockDim.x + threadIdx.x;
    if (idx < QKVC*CC) {
        int j = idx / CC, i = idx - j*CC;      // weffT[j][i]
        float acc = Wq[i*QKVC + j];
        #pragma unroll
        for (int r = 0; r < RR; r++)
            acc += LORA_SC * Aq[i*RR + r] * Bq[r*QKVC + j];
        g_weff[idx] = rnd_tf32(acc);
    } else if (idx < QKVC*CC + CC*CC) {
        int k = idx - QKVC*CC;
        int j = k / CC, i = k - j*CC;          // woutT[j][i]
        float acc = Wo[i*CC + j];
        #pragma unroll
        for (int r = 0; r < RR; r++)
            acc += LORA_SC * Ao[i*RR + r] * Bo[r*CC + j];
        g_wout[k] = rnd_tf32(acc);
    }
}

// ---------------------------------------------------------------------------
// tf32 mma GEMM, cp.async 2-stage pipeline, static stage addressing,
// running global pointers. C[M][N] = A[M][K]*Bt[N][K]^T (+bias).
// BM=64, BN=128, BK=32, K=512. 256 threads = 8 warps (2m x 4n).
// ---------------------------------------------------------------------------
#define GK 512
#define GNT 4           // 8-col n-tiles per warp
#define GAW (64*36)     // words per A stage
#define GBW (128*36)    // words per B stage

template<bool ROUND, bool CVTA>
__global__ __launch_bounds__(256, 2) void tf32_gemm(
    const float* __restrict__ A, const float* __restrict__ Bt,
    const float* __restrict__ bias, float* __restrict__ C, int N) {
    extern __shared__ uint32_t smg[];
    uint32_t smbase = (uint32_t)__cvta_generic_to_shared(smg);

    int tid = threadIdx.x;
    int warp = tid >> 5, lane = tid & 31;
    int wm = warp & 1, wn = warp >> 1;      // 2m x 4n
    int g = lane >> 2, tig = lane & 3;
    int bm = blockIdx.y * 64;
    int bn = blockIdx.x * 128;

    float acc[2][GNT][4];
    #pragma unroll
    for (int im = 0; im < 2; im++)
        #pragma unroll
        for (int nt = 0; nt < GNT; nt++)
            #pragma unroll
            for (int c = 0; c < 4; c++) acc[im][nt][c] = 0.f;

    // hoisted fragment smem word-offsets (relative to the stage base passed in)
    int aoff[2][2], boff[GNT];
    #pragma unroll
    for (int im = 0; im < 2; im++) {
        int r0 = wm*32 + im*16 + g;
        aoff[im][0] = r0*36 + 8*tig;
        aoff[im][1] = (r0+8)*36 + 8*tig;
    }
    #pragma unroll
    for (int nt = 0; nt < GNT; nt++)
        boff[nt] = (wn*32 + nt*8 + g)*36 + 8*tig;     // stage-relative (no 2*GAW)

    // running global pointers + fixed smem dst offsets
    int ua0 = tid, ua1 = tid + 256;           // A: 512 f4 per tile
    int ra0 = ua0 >> 3, ca0 = (ua0 & 7)*4;
    int ra1 = ua1 >> 3, ca1 = (ua1 & 7)*4;
    const float* aptr0 = &A[(size_t)(bm + ra0)*GK + ca0];
    const float* aptr1 = &A[(size_t)(bm + ra1)*GK + ca1];
    uint32_t dA0 = smbase + (ra0*36 + ca0)*4;
    uint32_t dA1 = smbase + (ra1*36 + ca1)*4;
    const float* bptr[4]; uint32_t dB[4];
    #pragma unroll
    for (int i = 0; i < 4; i++) {
        int u = tid + 256*i; int r = u >> 3, c4 = (u & 7)*4;
        bptr[i] = &Bt[(size_t)(bn + r)*GK + c4];
        dB[i] = smbase + (2*GAW + r*36 + c4)*4;
    }

    auto issue = [&](uint32_t sA, uint32_t sB) {
        cp16(dA0 + sA, aptr0); cp16(dA1 + sA, aptr1);
        aptr0 += 32; aptr1 += 32;
        #pragma unroll
        for (int i = 0; i < 4; i++) { cp16(dB[i] + sB, bptr[i]); bptr[i] += 32; }
    };

    auto compute = [&](const uint32_t* As, const uint32_t* Bs) {
        #pragma unroll
        for (int h = 0; h < 2; h++) {
            uint32_t Ar[2][2][4];
            #pragma unroll
            for (int im = 0; im < 2; im++) {
                *(uint4*)Ar[im][0] = *(const uint4*)&As[aoff[im][0] + 4*h];
                *(uint4*)Ar[im][1] = *(const uint4*)&As[aoff[im][1] + 4*h];
                if (CVTA) {
                    #pragma unroll
                    for (int q = 0; q < 4; q++) {
                        Ar[im][0][q] = u2tf32(Ar[im][0][q]);
                        Ar[im][1][q] = u2tf32(Ar[im][1][q]);
                    }
                }
            }
            uint32_t Br[GNT][4];
            #pragma unroll
            for (int nt = 0; nt < GNT; nt++)
                *(uint4*)Br[nt] = *(const uint4*)&Bs[boff[nt] + 4*h];
            #pragma unroll
            for (int im = 0; im < 2; im++)
                #pragma unroll
                for (int nt = 0; nt < GNT; nt++) {
                    MMA_TF32(acc[im][nt], Ar[im][0][0], Ar[im][1][0],
                             Ar[im][0][1], Ar[im][1][1], Br[nt][0], Br[nt][1]);
                    MMA_TF32(acc[im][nt], Ar[im][0][2], Ar[im][1][2],
                             Ar[im][0][3], Ar[im][1][3], Br[nt][2], Br[nt][3]);
                }
        }
    };

    // prologue: tile 0 -> stage 0
    issue(0, 0); CP_COMMIT;
    CP_WAIT(0);
    __syncthreads();

    // 16 k-tiles processed in pairs; stage addresses are compile-time constants
    #pragma unroll 1
    for (int tp = 0; tp < 8; tp++) {
        issue(GAW*4, GBW*4); CP_COMMIT;               // tile 2tp+1 -> stage 1
        compute(smg, smg + 2*GAW);                    // stage 0
        CP_WAIT(0); __syncthreads();
        if (tp < 7) { issue(0, 0); CP_COMMIT; }       // tile 2tp+2 -> stage 0
        compute(smg + GAW, smg + 2*GAW + GBW);        // stage 1
        CP_WAIT(0); __syncthreads();
    }

    #pragma unroll
    for (int nt = 0; nt < GNT; nt++) {
        int col = bn + wn*32 + nt*8 + tig*2;
        float b0 = 0.f, b1 = 0.f;
        if (bias) { b0 = bias[col]; b1 = bias[col+1]; }
        #pragma unroll
        for (int im = 0; im < 2; im++) {
            int row = bm + wm*32 + im*16 + g;
            float c0 = acc[im][nt][0] + b0, c1 = acc[im][nt][1] + b1;
            float c2 = acc[im][nt][2] + b0, c3 = acc[im][nt][3] + b1;
            if (ROUND) { c0 = rnd_tf32(c0); c1 = rnd_tf32(c1);
                         c2 = rnd_tf32(c2); c3 = rnd_tf32(c3); }
            *(float2*)&C[(size_t)row * N + col] = make_float2(c0, c1);
            *(float2*)&C[(size_t)(row + 8) * N + col] = make_float2(c2, c3);
        }
    }
}

// ---------------------------------------------------------------------------
// Attention (identical to R4/R5-verified version).
// ---------------------------------------------------------------------------
#define AT_QS 68
#define AT_KS 68
#define AT_VS 72
#define AT_SS 164

#define AOFF_V   0
#define AOFF_RED (AOFF_V + 160*AT_VS)
#define R_ML 0
#define R_MG 128
#define R_SL 192
#define R_SG 320
#define AOFF_Q   (AOFF_RED + 384)
#define AOFF_K   (AOFF_Q + 64*AT_QS)
#define AOFF_S   AOFF_Q
#define ATT_WORDS (AOFF_K + 160*AT_KS)

__global__ __launch_bounds__(256, 2) void attn_kernel() {
    extern __shared__ uint32_t sm[];
    float* smf = (float*)sm;
    uint32_t smbase = (uint32_t)__cvta_generic_to_shared(sm);

    const float* qkv = g_qkv;
    int qb = blockIdx.x, h = blockIdx.y, b = blockIdx.z;
    int tid = threadIdx.x;
    int warp = tid >> 5, lane = tid & 31;
    int g = lane >> 2, tig = lane & 3;
    int wm = warp & 3, wn = warp >> 2;
    int qstart = qb * 64;
    const float NEG = -1e30f;

    for (int u = tid; u < 6144; u += 256) {
        uint32_t dst; const float* src;
        if (u < 1024) {
            int r = u >> 4, c4 = u & 15;
            dst = AOFF_Q + r*AT_QS + c4*4;
            src = &qkv[((size_t)(b*NN + qstart + r))*QKVC + h*DH + c4*4];
        } else if (u < 3584) {
            int v = u - 1024; int r = v >> 4, c4 = v & 15;
            int kidx = (r < 128) ? max(qstart - 64 + r, 0) : (r - 128)*WIN;
            dst = AOFF_K + r*AT_KS + c4*4;
            src = &qkv[((size_t)(b*NN + kidx))*QKVC + h*DH + CC + c4*4];
        } else {
            int v = u - 3584; int r = v >> 4, c4 = v & 15;
            int kidx = (r < 128) ? max(qstart - 64 + r, 0) : (r - 128)*WIN;
            dst = AOFF_V + r*AT_VS + c4*4;
            src = &qkv[((size_t)(b*NN + kidx))*QKVC + h*DH + 2*CC + c4*4];
        }
        cp16(smbase + dst*4, src);
    }
    CP_COMMIT; CP_WAIT(0);
    __syncthreads();

    float acc[10][4];
    #pragma unroll
    for (int n = 0; n < 10; n++)
        #pragma unroll
        for (int c = 0; c < 4; c++) acc[n][c] = 0.f;

    int row0 = wm*16 + g, row1 = row0 + 8;
    #pragma unroll
    for (int ch = 0; ch < 2; ch++)
        #pragma unroll
        for (int hh = 0; hh < 2; hh++) {
            uint32_t Ar0[4], Ar1[4];
            *(uint4*)Ar0 = *(const uint4*)&sm[AOFF_Q + row0*AT_QS + ch*32 + 8*tig + 4*hh];
            *(uint4*)Ar1 = *(const uint4*)&sm[AOFF_Q + row1*AT_QS + ch*32 + 8*tig + 4*hh];
            uint32_t Br[10][4];
            #pragma unroll
            for (int nt = 0; nt < 10; nt++)
                *(uint4*)Br[nt] = *(const uint4*)&sm[AOFF_K + (wn*80 + nt*8 + g)*AT_KS
                                                     + ch*32 + 8*tig + 4*hh];
            #pragma unroll
            for (int nt = 0; nt < 10; nt++) {
                MMA_TF32(acc[nt], Ar0[0], Ar1[0], Ar0[1], Ar1[1], Br[nt][0], Br[nt][1]);
                MMA_TF32(acc[nt], Ar0[2], Ar1[2], Ar0[3], Ar1[3], Br[nt][2], Br[nt][3]);
            }
        }

    int minj = 64 - qstart;
    #pragma unroll
    for (int n = 0; n < 10; n++) {
        int cb = wn*80 + n*8;
        int c0 = cb + tig*2, c1 = c0 + 1;
        if (cb < 128) {
            bool v00 = (c0 >= row0) && (c0 <= row0 + 64) && (c0 >= minj);
            bool v01 = (c1 >= row0) && (c1 <= row0 + 64) && (c1 >= minj);
            bool v10 = (c0 >= row1) && (c0 <= row1 + 64) && (c0 >= minj);
            bool v11 = (c1 >= row1) && (c1 <= row1 + 64) && (c1 >= minj);
            acc[n][0] = v00 ? acc[n][0]*0.125f : NEG;
            acc[n][1] = v01 ? acc[n][1]*0.125f : NEG;
            acc[n][2] = v10 ? acc[n][2]*0.125f : NEG;
            acc[n][3] = v11 ? acc[n][3]*0.125f : NEG;
        } else {
            acc[n][0] *= 0.125f; acc[n][1] *= 0.125f;
            acc[n][2] *= 0.125f; acc[n][3] *= 0.125f;
        }
    }

    int nLoc = (wn == 0) ? 10 : 6;
    float m0 = NEG, m1 = NEG;
    for (int n = 0; n < nLoc; n++) {
        m0 = fmaxf(m0, fmaxf(acc[n][0], acc[n][1]));
        m1 = fmaxf(m1, fmaxf(acc[n][2], acc[n][3]));
    }
    m0 = fmaxf(m0, __shfl_xor_sync(0xffffffffu, m0, 1));
    m0 = fmaxf(m0, __shfl_xor_sync(0xffffffffu, m0, 2));
    m1 = fmaxf(m1, __shfl_xor_sync(0xffffffffu, m1, 1));
    m1 = fmaxf(m1, __shfl_xor_sync(0xffffffffu, m1, 2));
    float mg0 = NEG, mg1 = NEG;
    if (wn == 1) {
        for (int n = 6; n < 10; n++) {
            mg0 = fmaxf(mg0, fmaxf(acc[n][0], acc[n][1]));
            mg1 = fmaxf(mg1, fmaxf(acc[n][2], acc[n][3]));
        }
        mg0 = fmaxf(mg0, __shfl_xor_sync(0xffffffffu, mg0, 1));
        mg0 = fmaxf(mg0, __shfl_xor_sync(0xffffffffu, mg0, 2));
        mg1 = fmaxf(mg1, __shfl_xor_sync(0xffffffffu, mg1, 1));
        mg1 = fmaxf(mg1, __shfl_xor_sync(0xffffffffu, mg1, 2));
    }
    if (tig == 0) {
        smf[AOFF_RED + R_ML + wn*64 + row0] = m0;
        smf[AOFF_RED + R_ML + wn*64 + row1] = m1;
        if (wn == 1) {
            smf[AOFF_RED + R_MG + row0] = mg0;
            smf[AOFF_RED + R_MG + row1] = mg1;
        }
    }
    __syncthreads();

    float mL0 = fmaxf(smf[AOFF_RED + R_ML + row0], smf[AOFF_RED + R_ML + 64 + row0]);
    float mL1 = fmaxf(smf[AOFF_RED + R_ML + row1], smf[AOFF_RED + R_ML + 64 + row1]);
    float mG0 = smf[AOFF_RED + R_MG + row0];
    float mG1 = smf[AOFF_RED + R_MG + row1];

    float s0 = 0.f, s1 = 0.f, sg0 = 0.f, sg1 = 0.f;
    for (int n = 0; n < nLoc; n++) {
        acc[n][0] = __expf(acc[n][0] - mL0); s0 += acc[n][0];
        acc[n][1] = __expf(acc[n][1] - mL0); s0 += acc[n][1];
        acc[n][2] = __expf(acc[n][2] - mL1); s1 += acc[n][2];
        acc[n][3] = __expf(acc[n][3] - mL1); s1 += acc[n][3];
    }
    if (wn == 1) {
        for (int n = 6; n < 10; n++) {
            acc[n][0] = __expf(acc[n][0] - mG0); sg0 += acc[n][0];
            acc[n][1] = __expf(acc[n][1] - mG0); sg0 += acc[n][1];
            acc[n][2] = __expf(acc[n][2] - mG1); sg1 += acc[n][2];
            acc[n][3] = __expf(acc[n][3] - mG1); sg1 += acc[n][3];
        }
    }
    s0 += __shfl_xor_sync(0xffffffffu, s0, 1);
    s0 += __shfl_xor_sync(0xffffffffu, s0, 2);
    s1 += __shfl_xor_sync(0xffffffffu, s1, 1);
    s1 += __shfl_xor_sync(0xffffffffu, s1, 2);
    if (wn == 1) {
        sg0 += __shfl_xor_sync(0xffffffffu, sg0, 1);
        sg0 += __shfl_xor_sync(0xffffffffu, sg0, 2);
        sg1 += __shfl_xor_sync(0xffffffffu, sg1, 1);
        sg1 += __shfl_xor_sync(0xffffffffu, sg1, 2);
    }
    if (tig == 0) {
        smf[AOFF_RED + R_SL + wn*64 + row0] = s0;
        smf[AOFF_RED + R_SL + wn*64 + row1] = s1;
        if (wn == 1) {
            smf[AOFF_RED + R_SG + row0] = sg0;
            smf[AOFF_RED + R_SG + row1] = sg1;
        }
    }
    __syncthreads();

    float iL0 = 1.f / (smf[AOFF_RED + R_SL + row0] + smf[AOFF_RED + R_SL + 64 + row0]);
    float iL1 = 1.f / (smf[AOFF_RED + R_SL + row1] + smf[AOFF_RED + R_SL + 64 + row1]);
    float iG0 = 1.f / smf[AOFF_RED + R_SG + row0];
    float iG1 = 1.f / smf[AOFF_RED + R_SG + row1];

    #pragma unroll
    for (int n = 0; n < 10; n++) {
        int cb = wn*80 + n*8;
        int c0 = cb + tig*2;
        float f0, f1, f2, f3;
        if (n < nLoc || wn == 0) { f0 = acc[n][0]*iL0; f1 = acc[n][1]*iL0;
                                   f2 = acc[n][2]*iL1; f3 = acc[n][3]*iL1; }
        else                     { f0 = acc[n][0]*iG0; f1 = acc[n][1]*iG0;
                                   f2 = acc[n][2]*iG1; f3 = acc[n][3]*iG1; }
        sm[AOFF_S + row0*AT_SS + c0]     = f2tf32(f0);
        sm[AOFF_S + row0*AT_SS + c0 + 1] = f2tf32(f1);
        sm[AOFF_S + row1*AT_SS + c0]     = f2tf32(f2);
        sm[AOFF_S + row1*AT_SS + c0 + 1] = f2tf32(f3);
    }
    __syncthreads();

    float acc2[4][4];
    #pragma unroll
    for (int n = 0; n < 4; n++)
        #pragma unroll
        for (int c = 0; c < 4; c++) acc2[n][c] = 0.f;

    #pragma unroll
    for (int ks = 0; ks < 20; ks++) {
        int k0 = ks * 8;
        uint32_t a0 = sm[AOFF_S + row0*AT_SS + k0 + tig];
        uint32_t a1 = sm[AOFF_S + row1*AT_SS + k0 + tig];
        uint32_t a2 = sm[AOFF_S + row0*AT_SS + k0 + tig + 4];
        uint32_t a3 = sm[AOFF_S + row1*AT_SS + k0 + tig + 4];
        #pragma unroll
        for (int n = 0; n < 4; n++) {
            int cb = wn*32 + n*8;
            uint32_t b0 = sm[AOFF_V + (k0 + tig)*AT_VS + cb + g];
            uint32_t b1 = sm[AOFF_V + (k0 + tig + 4)*AT_VS + cb + g];
            MMA_TF32(acc2[n], a0, a1, a2, a3, b0, b1);
        }
    }

    #pragma unroll
    for (int n = 0; n < 4; n++) {
        int col = h*DH + wn*32 + n*8 + tig*2;
        size_t r0o = ((size_t)(b*NN + qstart + row0)) * CC + col;
        size_t r1o = ((size_t)(b*NN + qstart + row1)) * CC + col;
        *(float2*)&g_att[r0o] = make_float2(rnd_tf32(acc2[n][0]), rnd_tf32(acc2[n][1]));
        *(float2*)&g_att[r1o] = make_float2(rnd_tf32(acc2[n][2]), rnd_tf32(acc2[n][3]));
    }
}

// ---------------------------------------------------------------------------
// launch
// ---------------------------------------------------------------------------
extern "C" void kernel_launch(void* const* d_in, const int* in_sizes, int n_in,
                              void* d_out, int out_size) {
    const float* x       = (const float*)d_in[0];
    const float* w_qkv   = (const float*)d_in[1];
    const float* lA_qkv  = (const float*)d_in[2];
    const float* lB_qkv  = (const float*)d_in[3];
    const float* w_out   = (const float*)d_in[4];
    const float* b_out   = (const float*)d_in[5];
    const float* lA_out  = (const float*)d_in[6];
    const float* lB_out  = (const float*)d_in[7];
    float* out = (float*)d_out;

    float *p_weff, *p_wout, *p_qkv, *p_att;
    cudaGetSymbolAddress((void**)&p_weff, g_weff);
    cudaGetSymbolAddress((void**)&p_wout, g_wout);
    cudaGetSymbolAddress((void**)&p_qkv,  g_qkv);
    cudaGetSymbolAddress((void**)&p_att,  g_att);

    int gemm_smem = (2*GAW + 2*GBW) * 4;   // 55296 B

    // 1. prep: fold LoRA into transposed, rounded weights
    {
        int total = QKVC*CC + CC*CC;
        prep_kernel<<<(total + 255)/256, 256>>>(w_qkv, lA_qkv, lB_qkv,
                                                w_out, lA_out, lB_out);
    }
    // 2. qkv = x @ weffT^T  (A converted in-register, rounded output)
    {
        cudaFuncSetAttribute((const void*)tf32_gemm<true, true>,
                             cudaFuncAttributeMaxDynamicSharedMemorySize, gemm_smem);
        dim3 grid(QKVC/128, MTOT/64);
        tf32_gemm<true, true><<<grid, 256, gemm_smem>>>(x, p_weff, nullptr, p_qkv, QKVC);
    }
    // 3. attention
    {
        int smem = ATT_WORDS * 4;   // 108544
        cudaFuncSetAttribute((const void*)attn_kernel,
                             cudaFuncAttributeMaxDynamicSharedMemorySize, smem);
        dim3 grid(NN/64, HEADS, BB);
        attn_kernel<<<grid, 256, smem>>>();
    }
    // 4. out = att @ woutT^T + b_out
    {
        cudaFuncSetAttribute((const void*)tf32_gemm<false, false>,
                             cudaFuncAttributeMaxDynamicSharedMemorySize, gemm_smem);
        dim3 grid(CC/128, MTOT/64);
        tf32_gemm<false, false><<<grid, 256, gemm_smem>>>(p_att, p_wout, b_out, out, CC);
    }
}